// round 2
// baseline (speedup 1.0000x reference)
#include <cuda_runtime.h>
#include <cuda_bf16.h>
#include <math.h>

// Fixed problem shape (registry problem is fixed-shape): F=200000, B=4.
#define FMAX 200000
#define BMAX 4

// Scratch (device globals -- no allocation allowed in kernel_launch).
// Packed per-face record: 24 floats = 96B = exactly 3 L2 sectors, 16B aligned.
// Layout (float index):
//  0..5  : vt0.u vt0.v vt1.u vt1.v vt2.u vt2.v
//  6..14 : vn0.xyz vn1.xyz vn2.xyz
// 15..23 : v0.xyz  v1.xyz  v2.xyz
__device__ float4 g_packed[FMAX * 6];
// Per (b,f): {1/z0, 1/z1, 1/z2, 0} -- one aligned 16B load in main pass.
__device__ float4 g_invfz[BMAX * FMAX];

__global__ void pack_faces_kernel(const float* __restrict__ verts,
                                  const float* __restrict__ vts,
                                  const float* __restrict__ vns,
                                  const int* __restrict__ f_vt,
                                  const int* __restrict__ f_vn,
                                  const int* __restrict__ f_v,
                                  int F) {
    int f = blockIdx.x * blockDim.x + threadIdx.x;
    if (f >= F) return;
    float tmp[24];
#pragma unroll
    for (int k = 0; k < 3; k++) {
        int it = __ldg(&f_vt[f * 3 + k]);
        tmp[k * 2 + 0] = __ldg(&vts[it * 2 + 0]);
        tmp[k * 2 + 1] = __ldg(&vts[it * 2 + 1]);
    }
#pragma unroll
    for (int k = 0; k < 3; k++) {
        int in_ = __ldg(&f_vn[f * 3 + k]);
        tmp[6 + k * 3 + 0] = __ldg(&vns[in_ * 3 + 0]);
        tmp[6 + k * 3 + 1] = __ldg(&vns[in_ * 3 + 1]);
        tmp[6 + k * 3 + 2] = __ldg(&vns[in_ * 3 + 2]);
    }
#pragma unroll
    for (int k = 0; k < 3; k++) {
        int iv = __ldg(&f_v[f * 3 + k]);
        tmp[15 + k * 3 + 0] = __ldg(&verts[iv * 3 + 0]);
        tmp[15 + k * 3 + 1] = __ldg(&verts[iv * 3 + 1]);
        tmp[15 + k * 3 + 2] = __ldg(&verts[iv * 3 + 2]);
    }
    float4* dst = g_packed + f * 6;
#pragma unroll
    for (int i = 0; i < 6; i++)
        dst[i] = make_float4(tmp[4 * i + 0], tmp[4 * i + 1],
                             tmp[4 * i + 2], tmp[4 * i + 3]);
}

__global__ void pack_fz_kernel(const float* __restrict__ fuvz, int BF) {
    int i = blockIdx.x * blockDim.x + threadIdx.x;
    if (i >= BF) return;
    const float* s = fuvz + (size_t)i * 9;  // faces_v_uvz[b,f,:,:] record (coalesced region)
    float4 o;
    o.x = 1.0f / __ldg(&s[2]);
    o.y = 1.0f / __ldg(&s[5]);
    o.z = 1.0f / __ldg(&s[8]);
    o.w = 0.0f;
    g_invfz[i] = o;
}

__global__ void raster_main_kernel(const int* __restrict__ fidx_map,
                                   const float* __restrict__ depth,
                                   const float* __restrict__ weight,
                                   const float* __restrict__ pose,
                                   float* __restrict__ out,
                                   int HW, int F, int total) {
    int gid = blockIdx.x * blockDim.x + threadIdx.x;
    if (gid >= total) return;
    int b = gid / HW;   // uniform within a block (HW % blockDim == 0)

    int f = __ldg(&fidx_map[gid]);
    float d = __ldg(&depth[gid]);
    float w0 = __ldg(&weight[gid * 3 + 0]);
    float w1 = __ldg(&weight[gid * 3 + 1]);
    float w2 = __ldg(&weight[gid * 3 + 2]);

    float4 iz = g_invfz[b * F + f];
    float c0 = iz.x * w0 * d;
    float c1 = iz.y * w1 * d;
    float c2 = iz.z * w2 * d;

    const float4* rec = g_packed + f * 6;
    float4 r0 = rec[0], r1 = rec[1], r2 = rec[2];
    float4 r3 = rec[3], r4 = rec[4], r5 = rec[5];

    // uv
    float u = r0.x * c0 + r0.z * c1 + r1.x * c2;
    float v = r0.y * c0 + r0.w * c1 + r1.y * c2;
    u = u - floorf(u);
    v = v - floorf(v);

    // normal sum
    float nx = r1.z * c0 + r2.y * c1 + r3.x * c2;
    float ny = r1.w * c0 + r2.z * c1 + r3.y * c2;
    float nz = r2.x * c0 + r2.w * c1 + r3.z * c2;
    float nl = sqrtf(nx * nx + ny * ny + nz * nz);
    float inl = 1.0f / fmaxf(nl, 1e-12f);
    float Nx = nx * inl, Ny = ny * inl, Nz = nz * inl;

    // position sum
    float px = r3.w * c0 + r4.z * c1 + r5.y * c2;
    float py = r4.x * c0 + r4.w * c1 + r5.z * c2;
    float pz = r4.y * c0 + r5.x * c1 + r5.w * c2;

    // pose: R (3x3) + t (3), row-major 4x4. b is block-uniform -> broadcast loads.
    const float* P = pose + b * 16;
    float R00 = __ldg(&P[0]), R01 = __ldg(&P[1]), R02 = __ldg(&P[2]),  t0 = __ldg(&P[3]);
    float R10 = __ldg(&P[4]), R11 = __ldg(&P[5]), R12 = __ldg(&P[6]),  t1 = __ldg(&P[7]);
    float R20 = __ldg(&P[8]), R21 = __ldg(&P[9]), R22 = __ldg(&P[10]), t2 = __ldg(&P[11]);

    // normal in camera frame, renormalized (matches reference: normalize(R @ normalize(n)))
    float mx = R00 * Nx + R01 * Ny + R02 * Nz;
    float my = R10 * Nx + R11 * Ny + R12 * Nz;
    float mz = R20 * Nx + R21 * Ny + R22 * Nz;
    float ml = sqrtf(mx * mx + my * my + mz * mz);
    float iml = 1.0f / fmaxf(ml, 1e-12f);
    mx *= iml; my *= iml; mz *= iml;

    // position in camera frame
    float qx = R00 * px + R01 * py + R02 * pz + t0;
    float qy = R10 * px + R11 * py + R12 * pz + t1;
    float qz = R20 * px + R21 * py + R22 * pz + t2;

    size_t o = (size_t)gid * 14;
    out[o + 0] = u;   out[o + 1] = v;
    out[o + 2] = Nx;  out[o + 3] = Ny;  out[o + 4] = Nz;
    out[o + 5] = mx;  out[o + 6] = my;  out[o + 7] = mz;
    out[o + 8] = px;  out[o + 9] = py;  out[o + 10] = pz;
    out[o + 11] = qx; out[o + 12] = qy; out[o + 13] = qz;
}

extern "C" void kernel_launch(void* const* d_in, const int* in_sizes, int n_in,
                              void* d_out, int out_size) {
    const float* vertices = (const float*)d_in[0];   // (1,V,3)
    const float* vt       = (const float*)d_in[1];   // (1,V,2)
    const float* vn       = (const float*)d_in[2];   // (1,V,3)
    const int*   f_vt     = (const int*)d_in[3];     // (1,F,3)
    const int*   f_vn     = (const int*)d_in[4];     // (1,F,3)
    const int*   f_v      = (const int*)d_in[5];     // (1,F,3)
    const float* pose     = (const float*)d_in[6];   // (B,4,4)
    const float* depth    = (const float*)d_in[7];   // (B,H,W)
    const int*   fim      = (const int*)d_in[8];     // (B,H,W)
    const float* wm       = (const float*)d_in[9];   // (B,H,W,3)
    // d_in[10] = v_uvz: dead code in reference (v_front_mask unused)
    const float* fuvz     = (const float*)d_in[11];  // (B,F,3,3)

    int F   = in_sizes[3] / 3;
    int B   = in_sizes[6] / 16;
    int BHW = in_sizes[7];
    int HW  = BHW / B;
    int BF  = B * F;

    pack_faces_kernel<<<(F + 255) / 256, 256>>>(vertices, vt, vn, f_vt, f_vn, f_v, F);
    pack_fz_kernel<<<(BF + 255) / 256, 256>>>(fuvz, BF);
    raster_main_kernel<<<(BHW + 255) / 256, 256>>>(fim, depth, wm, pose,
                                                   (float*)d_out, HW, F, BHW);
}

// round 3
// speedup vs baseline: 2.5425x; 2.5425x over previous
#include <cuda_runtime.h>
#include <cuda_bf16.h>
#include <math.h>

// Fixed problem shape: F=200000, B=4.
#define FMAX 200000
#define BMAX 4

// Packed per-face record: 24 floats = 96B = exactly 3 L2 sectors, 16B aligned.
//  0..5  : vt0.u vt0.v vt1.u vt1.v vt2.u vt2.v
//  6..14 : vn0.xyz vn1.xyz vn2.xyz
// 15..23 : v0.xyz  v1.xyz  v2.xyz
__device__ float4 g_packed[FMAX * 6];
// Per (b,f): {1/z0, 1/z1, 1/z2, 0}
__device__ float4 g_invfz[BMAX * FMAX];

// One thread per (face, corner): coalesced index loads, 8 gathers each.
__global__ void pack_faces_kernel(const float* __restrict__ verts,
                                  const float* __restrict__ vts,
                                  const float* __restrict__ vns,
                                  const int* __restrict__ f_vt,
                                  const int* __restrict__ f_vn,
                                  const int* __restrict__ f_v,
                                  int F3) {
    int i = blockIdx.x * blockDim.x + threadIdx.x;
    if (i >= F3) return;
    int f = i / 3, k = i - f * 3;
    int it  = __ldg(&f_vt[i]);
    int in_ = __ldg(&f_vn[i]);
    int iv  = __ldg(&f_v[i]);
    float* rec = (float*)(g_packed + f * 6);
    rec[k * 2 + 0]      = __ldg(&vts[it * 2 + 0]);
    rec[k * 2 + 1]      = __ldg(&vts[it * 2 + 1]);
    rec[6 + k * 3 + 0]  = __ldg(&vns[in_ * 3 + 0]);
    rec[6 + k * 3 + 1]  = __ldg(&vns[in_ * 3 + 1]);
    rec[6 + k * 3 + 2]  = __ldg(&vns[in_ * 3 + 2]);
    rec[15 + k * 3 + 0] = __ldg(&verts[iv * 3 + 0]);
    rec[15 + k * 3 + 1] = __ldg(&verts[iv * 3 + 1]);
    rec[15 + k * 3 + 2] = __ldg(&verts[iv * 3 + 2]);
}

__global__ void pack_fz_kernel(const float* __restrict__ fuvz, int BF) {
    int i = blockIdx.x * blockDim.x + threadIdx.x;
    if (i >= BF) return;
    const float* s = fuvz + (size_t)i * 9;
    float4 o;
    o.x = 1.0f / __ldcs(&s[2]);
    o.y = 1.0f / __ldcs(&s[5]);
    o.z = 1.0f / __ldcs(&s[8]);
    o.w = 0.0f;
    g_invfz[i] = o;
}

#define BLK 256

__global__ __launch_bounds__(BLK) void raster_main_kernel(
        const int* __restrict__ fidx_map,
        const float* __restrict__ depth,
        const float* __restrict__ weight,
        const float* __restrict__ pose,
        float* __restrict__ out,
        int HW, int F, int total) {
    __shared__ float sm[BLK * 14];

    int tid = threadIdx.x;
    int gid = blockIdx.x * BLK + tid;
    bool active = (gid < total);
    int b = active ? (gid / HW) : 0;

    float vals[14];
#pragma unroll
    for (int j = 0; j < 14; j++) vals[j] = 0.0f;

    if (active) {
        int f = __ldcs(&fidx_map[gid]);
        float d  = __ldcs(&depth[gid]);
        float w0 = __ldcs(&weight[gid * 3 + 0]);
        float w1 = __ldcs(&weight[gid * 3 + 1]);
        float w2 = __ldcs(&weight[gid * 3 + 2]);

        float4 iz = g_invfz[b * F + f];
        float c0 = iz.x * w0 * d;
        float c1 = iz.y * w1 * d;
        float c2 = iz.z * w2 * d;

        const float4* rec = g_packed + f * 6;
        float4 r0 = rec[0], r1 = rec[1], r2 = rec[2];
        float4 r3 = rec[3], r4 = rec[4], r5 = rec[5];

        // uv
        float u = r0.x * c0 + r0.z * c1 + r1.x * c2;
        float v = r0.y * c0 + r0.w * c1 + r1.y * c2;
        u = u - floorf(u);
        v = v - floorf(v);

        // normal sum + normalize
        float nx = r1.z * c0 + r2.y * c1 + r3.x * c2;
        float ny = r1.w * c0 + r2.z * c1 + r3.y * c2;
        float nz = r2.x * c0 + r2.w * c1 + r3.z * c2;
        float nl = sqrtf(nx * nx + ny * ny + nz * nz);
        float inl = 1.0f / fmaxf(nl, 1e-12f);
        float Nx = nx * inl, Ny = ny * inl, Nz = nz * inl;

        // position sum
        float px = r3.w * c0 + r4.z * c1 + r5.y * c2;
        float py = r4.x * c0 + r4.w * c1 + r5.z * c2;
        float pz = r4.y * c0 + r5.x * c1 + r5.w * c2;

        // pose (b block-uniform -> broadcast)
        const float* P = pose + b * 16;
        float R00 = __ldg(&P[0]), R01 = __ldg(&P[1]), R02 = __ldg(&P[2]),  t0 = __ldg(&P[3]);
        float R10 = __ldg(&P[4]), R11 = __ldg(&P[5]), R12 = __ldg(&P[6]),  t1 = __ldg(&P[7]);
        float R20 = __ldg(&P[8]), R21 = __ldg(&P[9]), R22 = __ldg(&P[10]), t2 = __ldg(&P[11]);

        float mx = R00 * Nx + R01 * Ny + R02 * Nz;
        float my = R10 * Nx + R11 * Ny + R12 * Nz;
        float mz = R20 * Nx + R21 * Ny + R22 * Nz;
        float ml = sqrtf(mx * mx + my * my + mz * mz);
        float iml = 1.0f / fmaxf(ml, 1e-12f);
        mx *= iml; my *= iml; mz *= iml;

        float qx = R00 * px + R01 * py + R02 * pz + t0;
        float qy = R10 * px + R11 * py + R12 * pz + t1;
        float qz = R20 * px + R21 * py + R22 * pz + t2;

        vals[0] = u;   vals[1] = v;
        vals[2] = Nx;  vals[3] = Ny;  vals[4] = Nz;
        vals[5] = mx;  vals[6] = my;  vals[7] = mz;
        vals[8] = px;  vals[9] = py;  vals[10] = pz;
        vals[11] = qx; vals[12] = qy; vals[13] = qz;
    }

    // Stage to smem, then coalesced float4 streaming stores.
#pragma unroll
    for (int j = 0; j < 14; j++) sm[tid * 14 + j] = vals[j];
    __syncthreads();

    size_t blk_base = (size_t)blockIdx.x * BLK * 14;   // float offset; *4 bytes is 16B-aligned
    const float4* sm4 = (const float4*)sm;
    float4* out4 = (float4*)(out + blk_base);
    int nfloat4 = (BLK * 14) / 4;                      // 896
    size_t limit4 = ((size_t)total * 14 - blk_base) / 4;
#pragma unroll
    for (int idx = 0; idx < nfloat4 / BLK + 1; idx++) {
        int e = idx * BLK + tid;
        if (e < nfloat4 && (size_t)e < limit4)
            __stcs(&out4[e], sm4[e]);
    }
}

extern "C" void kernel_launch(void* const* d_in, const int* in_sizes, int n_in,
                              void* d_out, int out_size) {
    const float* vertices = (const float*)d_in[0];   // (1,V,3)
    const float* vt       = (const float*)d_in[1];   // (1,V,2)
    const float* vn       = (const float*)d_in[2];   // (1,V,3)
    const int*   f_vt     = (const int*)d_in[3];     // (1,F,3)
    const int*   f_vn     = (const int*)d_in[4];     // (1,F,3)
    const int*   f_v      = (const int*)d_in[5];     // (1,F,3)
    const float* pose     = (const float*)d_in[6];   // (B,4,4)
    const float* depth    = (const float*)d_in[7];   // (B,H,W)
    const int*   fim      = (const int*)d_in[8];     // (B,H,W)
    const float* wm       = (const float*)d_in[9];   // (B,H,W,3)
    // d_in[10] = v_uvz: dead code in reference
    const float* fuvz     = (const float*)d_in[11];  // (B,F,3,3)

    int F3  = in_sizes[3];
    int F   = F3 / 3;
    int B   = in_sizes[6] / 16;
    int BHW = in_sizes[7];
    int HW  = BHW / B;
    int BF  = B * F;

    pack_faces_kernel<<<(F3 + 255) / 256, 256>>>(vertices, vt, vn, f_vt, f_vn, f_v, F3);
    pack_fz_kernel<<<(BF + 255) / 256, 256>>>(fuvz, BF);
    raster_main_kernel<<<(BHW + BLK - 1) / BLK, BLK>>>(fim, depth, wm, pose,
                                                       (float*)d_out, HW, F, BHW);
}

// round 4
// speedup vs baseline: 2.5562x; 1.0054x over previous
#include <cuda_runtime.h>
#include <cuda_bf16.h>
#include <math.h>

// Fixed problem shape: F=200000, B=4, V=100000.
#define FMAX 200000
#define BMAX 4
#define VMAX 100000

// Packed per-face record, padded to 128B (one L2 line), 128B-aligned.
// float layout within record (chunks = float4 index 0..7; 6..7 padding):
//  0..5  : vt0.u vt0.v vt1.u vt1.v vt2.u vt2.v
//  6..14 : vn0.xyz vn1.xyz vn2.xyz
// 15..23 : v0.xyz  v1.xyz  v2.xyz
__device__ __align__(128) float4 g_packed[FMAX * 8];
// Per (b,f): {1/z0, 1/z1, 1/z2, 0}
__device__ float4 g_invfz[BMAX * FMAX];
// float4-expanded vertex attribute arrays (one aligned LDG.128 per gather)
__device__ float4 g_verts4[VMAX];
__device__ float4 g_vns4[VMAX];

// ---------- pass 1: expand verts/vns to float4 (streamed, coalesced) ----------
__global__ void expand_kernel(const float* __restrict__ verts,
                              const float* __restrict__ vns, int V) {
    int i = blockIdx.x * blockDim.x + threadIdx.x;
    if (i >= V) return;
    g_verts4[i] = make_float4(__ldcs(&verts[3 * i]), __ldcs(&verts[3 * i + 1]),
                              __ldcs(&verts[3 * i + 2]), 0.0f);
    g_vns4[i]   = make_float4(__ldcs(&vns[3 * i]), __ldcs(&vns[3 * i + 1]),
                              __ldcs(&vns[3 * i + 2]), 0.0f);
}

// ---------- pass 2: fused face-record packing + inv-fz packing ----------
// Blocks [0, blocksF): pack 64 faces each (192 gather threads, 256 store threads).
// Blocks [blocksF, ...): pack_fz streaming.
#define PF_FACES 64
__global__ __launch_bounds__(256) void pack_fused_kernel(
        const float* __restrict__ vts,
        const int* __restrict__ f_vt,
        const int* __restrict__ f_vn,
        const int* __restrict__ f_v,
        const float* __restrict__ fuvz,
        int F, int blocksF, int BF) {
    int tid = threadIdx.x;
    if ((int)blockIdx.x < blocksF) {
        __shared__ float4 s_rec[PF_FACES * 8];
        float* s = (float*)s_rec;
        int fbase = blockIdx.x * PF_FACES;
        if (tid < PF_FACES * 3) {
            int fl = tid / 3, k = tid - fl * 3;
            int gi = (fbase + fl) * 3 + k;          // == fbase*3 + tid (coalesced)
            int it  = __ldg(&f_vt[gi]);
            int in_ = __ldg(&f_vn[gi]);
            int iv  = __ldg(&f_v[gi]);
            float2 t2 = __ldg((const float2*)vts + it);
            float4 n4 = __ldg(&g_vns4[in_]);
            float4 v4 = __ldg(&g_verts4[iv]);
            float* rec = s + fl * 32;
            rec[k * 2 + 0] = t2.x;  rec[k * 2 + 1] = t2.y;
            rec[6 + 3 * k + 0] = n4.x; rec[6 + 3 * k + 1] = n4.y; rec[6 + 3 * k + 2] = n4.z;
            rec[15 + 3 * k + 0] = v4.x; rec[15 + 3 * k + 1] = v4.y; rec[15 + 3 * k + 2] = v4.z;
        }
        __syncthreads();
        float4* dst = g_packed + (size_t)fbase * 8;
#pragma unroll
        for (int j = 0; j < 2; j++)
            dst[j * 256 + tid] = s_rec[j * 256 + tid];
    } else {
        int i = (blockIdx.x - blocksF) * 256 + tid;
        if (i >= BF) return;
        const float* sp = fuvz + (size_t)i * 9;
        float4 o;
        o.x = 1.0f / __ldcs(&sp[2]);
        o.y = 1.0f / __ldcs(&sp[5]);
        o.z = 1.0f / __ldcs(&sp[8]);
        o.w = 0.0f;
        g_invfz[i] = o;
    }
}

// ---------- pass 3: main per-pixel kernel ----------
#define BLK 256

__global__ __launch_bounds__(BLK) void raster_main_kernel(
        const int* __restrict__ fidx_map,
        const float* __restrict__ depth,
        const float* __restrict__ weight,
        const float* __restrict__ pose,
        float* __restrict__ out,
        int HW, int F, int total) {
    // s_rec: stride 7 float4 per pixel (112B -> conflict-free LDS.128 readback).
    // Reused as output staging after records are consumed.
    __shared__ float4 s_rec[BLK * 7];
    __shared__ int s_fidx[BLK];

    int tid = threadIdx.x;
    int gid = blockIdx.x * BLK + tid;
    bool active = (gid < total);
    int b = (blockIdx.x * BLK) / HW;   // uniform per block (BLK | HW)

    int f = 0;
    float d = 0.f, w0 = 0.f, w1 = 0.f, w2 = 0.f;
    float4 iz = make_float4(0.f, 0.f, 0.f, 0.f);
    if (active) {
        f  = __ldcs(&fidx_map[gid]);
        d  = __ldcs(&depth[gid]);
        w0 = __ldcs(&weight[gid * 3 + 0]);
        w1 = __ldcs(&weight[gid * 3 + 1]);
        w2 = __ldcs(&weight[gid * 3 + 2]);
        iz = g_invfz[b * F + f];
    }
    s_fidx[tid] = f;
    __syncthreads();

    // Cooperative record gather: 6 chunks x 256 pixels, consecutive ids hit
    // consecutive chunks of the same pixel's 128B-aligned record -> ~6 lines
    // per warp-iteration instead of 32.
#pragma unroll
    for (int i = 0; i < 6; i++) {
        int id = i * BLK + tid;
        int p = id / 6;
        int c = id - p * 6;
        int fp = s_fidx[p];
        s_rec[p * 7 + c] = g_packed[(size_t)fp * 8 + c];
    }
    __syncthreads();

    float vals[14];
#pragma unroll
    for (int j = 0; j < 14; j++) vals[j] = 0.0f;

    if (active) {
        const float4* rp = s_rec + tid * 7;
        float4 r0 = rp[0], r1 = rp[1], r2 = rp[2];
        float4 r3 = rp[3], r4 = rp[4], r5 = rp[5];

        float c0 = iz.x * w0 * d;
        float c1 = iz.y * w1 * d;
        float c2 = iz.z * w2 * d;

        // uv
        float u = r0.x * c0 + r0.z * c1 + r1.x * c2;
        float v = r0.y * c0 + r0.w * c1 + r1.y * c2;
        u = u - floorf(u);
        v = v - floorf(v);

        // normal sum + normalize
        float nx = r1.z * c0 + r2.y * c1 + r3.x * c2;
        float ny = r1.w * c0 + r2.z * c1 + r3.y * c2;
        float nz = r2.x * c0 + r2.w * c1 + r3.z * c2;
        float nl = sqrtf(nx * nx + ny * ny + nz * nz);
        float inl = 1.0f / fmaxf(nl, 1e-12f);
        float Nx = nx * inl, Ny = ny * inl, Nz = nz * inl;

        // position sum
        float px = r3.w * c0 + r4.z * c1 + r5.y * c2;
        float py = r4.x * c0 + r4.w * c1 + r5.z * c2;
        float pz = r4.y * c0 + r5.x * c1 + r5.w * c2;

        // pose (b block-uniform -> broadcast loads)
        const float* P = pose + b * 16;
        float R00 = __ldg(&P[0]), R01 = __ldg(&P[1]), R02 = __ldg(&P[2]),  t0 = __ldg(&P[3]);
        float R10 = __ldg(&P[4]), R11 = __ldg(&P[5]), R12 = __ldg(&P[6]),  t1 = __ldg(&P[7]);
        float R20 = __ldg(&P[8]), R21 = __ldg(&P[9]), R22 = __ldg(&P[10]), t2 = __ldg(&P[11]);

        float mx = R00 * Nx + R01 * Ny + R02 * Nz;
        float my = R10 * Nx + R11 * Ny + R12 * Nz;
        float mz = R20 * Nx + R21 * Ny + R22 * Nz;
        float ml = sqrtf(mx * mx + my * my + mz * mz);
        float iml = 1.0f / fmaxf(ml, 1e-12f);
        mx *= iml; my *= iml; mz *= iml;

        float qx = R00 * px + R01 * py + R02 * pz + t0;
        float qy = R10 * px + R11 * py + R12 * pz + t1;
        float qz = R20 * px + R21 * py + R22 * pz + t2;

        vals[0] = u;   vals[1] = v;
        vals[2] = Nx;  vals[3] = Ny;  vals[4] = Nz;
        vals[5] = mx;  vals[6] = my;  vals[7] = mz;
        vals[8] = px;  vals[9] = py;  vals[10] = pz;
        vals[11] = qx; vals[12] = qy; vals[13] = qz;
    }

    // Reuse s_rec as float staging for coalesced output stores.
    __syncthreads();
    float* sm = (float*)s_rec;
#pragma unroll
    for (int j = 0; j < 14; j++) sm[tid * 14 + j] = vals[j];
    __syncthreads();

    size_t blk_base = (size_t)blockIdx.x * BLK * 14;
    const float4* sm4 = (const float4*)sm;
    float4* out4 = (float4*)(out + blk_base);
    int nfloat4 = (BLK * 14) / 4;                      // 896
    size_t limit4 = ((size_t)total * 14 - blk_base) / 4;
#pragma unroll
    for (int idx = 0; idx < nfloat4 / BLK + 1; idx++) {
        int e = idx * BLK + tid;
        if (e < nfloat4 && (size_t)e < limit4)
            __stcs(&out4[e], sm4[e]);
    }
}

extern "C" void kernel_launch(void* const* d_in, const int* in_sizes, int n_in,
                              void* d_out, int out_size) {
    const float* vertices = (const float*)d_in[0];   // (1,V,3)
    const float* vt       = (const float*)d_in[1];   // (1,V,2)
    const float* vn       = (const float*)d_in[2];   // (1,V,3)
    const int*   f_vt     = (const int*)d_in[3];     // (1,F,3)
    const int*   f_vn     = (const int*)d_in[4];     // (1,F,3)
    const int*   f_v      = (const int*)d_in[5];     // (1,F,3)
    const float* pose     = (const float*)d_in[6];   // (B,4,4)
    const float* depth    = (const float*)d_in[7];   // (B,H,W)
    const int*   fim      = (const int*)d_in[8];     // (B,H,W)
    const float* wm       = (const float*)d_in[9];   // (B,H,W,3)
    // d_in[10] = v_uvz: dead code in reference
    const float* fuvz     = (const float*)d_in[11];  // (B,F,3,3)

    int V   = in_sizes[0] / 3;
    int F   = in_sizes[3] / 3;
    int B   = in_sizes[6] / 16;
    int BHW = in_sizes[7];
    int HW  = BHW / B;
    int BF  = B * F;

    int blocksF  = (F + PF_FACES - 1) / PF_FACES;
    int blocksFZ = (BF + 255) / 256;

    expand_kernel<<<(V + 255) / 256, 256>>>(vertices, vn, V);
    pack_fused_kernel<<<blocksF + blocksFZ, 256>>>(vt, f_vt, f_vn, f_v, fuvz,
                                                   F, blocksF, BF);
    raster_main_kernel<<<(BHW + BLK - 1) / BLK, BLK>>>(fim, depth, wm, pose,
                                                       (float*)d_out, HW, F, BHW);
}